// round 1
// baseline (speedup 1.0000x reference)
#include <cuda_runtime.h>

// EMA along last axis: acc_t = w*x_t + (1-w)*acc_{t-1}
// Shapes: mag_spec [B,C,F,T] fp32 (T=6000 contiguous), initial_state [B,C,F,1],
// weights [1]. Output [B,C,F,T] fp32.
//
// One block per sequence. Whole sequence (24KB) staged in shared memory.
// Decoupled chunked scan: per-thread local scan (zero init) + affine
// Hillis-Steele scan over chunk carries (constant coefficient a^L).

constexpr int T_LEN = 6000;
constexpr int NT    = 512;
constexpr int L     = 12;              // chunk length per thread
constexpr int NCH   = T_LEN / L;       // 500 active threads

__global__ __launch_bounds__(NT, 4)
void ema_kernel(const float* __restrict__ x,
                const float* __restrict__ init,
                const float* __restrict__ wptr,
                float* __restrict__ out)
{
    __shared__ float s[T_LEN];     // 24000 B
    __shared__ float carry[NT];    // 2048 B

    const int seq = blockIdx.x;
    const int t   = threadIdx.x;

    const float* xs = x   + (size_t)seq * T_LEN;
    float*       os = out + (size_t)seq * T_LEN;

    float w = wptr[0];
    w = fminf(fmaxf(w, 0.0f), 1.0f);
    const float a = 1.0f - w;

    // ---- 1. coalesced load of the full sequence into smem (float4) ----
    {
        const float4* x4 = reinterpret_cast<const float4*>(xs);
        float4*       s4 = reinterpret_cast<float4*>(s);
        #pragma unroll
        for (int i = t; i < T_LEN / 4; i += NT) s4[i] = x4[i];
    }
    __syncthreads();

    // ---- 2. per-thread local scan with zero initial state ----
    const bool active = (t < NCH);
    float local[L];
    float acc = 0.0f;
    if (active) {
        #pragma unroll
        for (int k = 0; k < L; k++) {
            acc = fmaf(w, s[t * L + k], a * acc);
            local[k] = acc;
        }
    }
    carry[t] = active ? acc : 0.0f;

    // a^L (compile-time-unrolled product)
    float aL = 1.0f;
    #pragma unroll
    for (int k = 0; k < L; k++) aL *= a;

    __syncthreads();

    // ---- 3. affine Hillis-Steele scan over carries:
    //         D_t = e_t + aL * D_{t-1}  (inclusive) ----
    float scale = aL;  // aL^(2^step)
    #pragma unroll
    for (int sft = 1; sft < NT; sft <<= 1) {
        float v    = carry[t];
        float prev = (t >= sft) ? carry[t - sft] : 0.0f;
        __syncthreads();
        carry[t] = fmaf(scale, prev, v);
        scale *= scale;
        __syncthreads();
    }

    // ---- 4. apply incoming state algebraically and write back to smem ----
    if (active) {
        // incoming acc for this chunk: C = aL^t * init + D_{t-1}
        float c = (t > 0) ? carry[t - 1] : 0.0f;
        float p = powf(aL, (float)t);        // underflows to 0 for large t (exact limit)
        c = fmaf(p, init[seq], c);

        // y_k = local_k + a^{k+1} * C   (independent FMAs, no chain)
        float pw = a;
        #pragma unroll
        for (int k = 0; k < L; k++) {
            s[t * L + k] = fmaf(pw, c, local[k]);
            pw *= a;
        }
    }
    __syncthreads();

    // ---- 5. coalesced store ----
    {
        const float4* s4 = reinterpret_cast<const float4*>(s);
        float4*       o4 = reinterpret_cast<float4*>(os);
        #pragma unroll
        for (int i = t; i < T_LEN / 4; i += NT) o4[i] = s4[i];
    }
}

extern "C" void kernel_launch(void* const* d_in, const int* in_sizes, int n_in,
                              void* d_out, int out_size)
{
    const float* x    = (const float*)d_in[0];   // mag_spec  [B,C,F,T]
    const float* init = (const float*)d_in[1];   // initial_state [B,C,F,1]
    const float* wp   = (const float*)d_in[2];   // weights [1]
    float*       out  = (float*)d_out;

    const int nseq = in_sizes[1];                // B*C*F = 4112
    ema_kernel<<<nseq, NT>>>(x, init, wp, out);
}